// round 1
// baseline (speedup 1.0000x reference)
#include <cuda_runtime.h>
#include <math.h>

// ---------------- problem constants (fixed shapes) ----------------
#define S_TOK   32760          // T*L
#define D_MODEL 2048
#define N_HEADS 16
#define D_HEAD  128
#define T_GRID  21
#define L_TOK   1560
#define A_TOK   64
#define KV_ROWS (T_GRID * A_TOK)   // 1344
#define EPS     1e-5f
#define ATT_SCALE 0.08838834764831845f   // 1/sqrt(128)

// ---------------- scratch (device globals: allocation-free) ----------------
__device__ float g_q[(size_t)S_TOK * D_MODEL];
__device__ float g_att[(size_t)S_TOK * D_MODEL];
__device__ float g_k[(size_t)KV_ROWS * D_MODEL];
__device__ float g_v[(size_t)KV_ROWS * D_MODEL];
__device__ float g_pos[S_TOK];
__device__ float g_mm[4];   // smin[0..1], smax[0..1]

// ---------------- per-stream min/max ----------------
__global__ void minmax_kernel(const float* __restrict__ maps, float* __restrict__ mm) {
    __shared__ float smn[256], smx[256];
    int st = blockIdx.x;
    const float* p = maps + (size_t)st * S_TOK;
    float mn = 3.4e38f, mx = -3.4e38f;
    for (int i = threadIdx.x; i < S_TOK; i += 256) {
        float v = p[i];
        mn = fminf(mn, v); mx = fmaxf(mx, v);
    }
    int t = threadIdx.x;
    smn[t] = mn; smx[t] = mx;
    __syncthreads();
    for (int o = 128; o > 0; o >>= 1) {
        if (t < o) { smn[t] = fminf(smn[t], smn[t + o]); smx[t] = fmaxf(smx[t], smx[t + o]); }
        __syncthreads();
    }
    if (t == 0) { mm[st] = smn[0]; mm[2 + st] = smx[0]; }
}

// ---------------- per-token position ids ----------------
__global__ void pos_kernel(const float* __restrict__ maps, const float* __restrict__ mm,
                           float* __restrict__ pos) {
    int n = blockIdx.x * blockDim.x + threadIdx.x;
    if (n >= S_TOK) return;
    float m0 = maps[n];
    float m1 = maps[S_TOK + n];
    int w = (m1 > m0) ? 1 : 0;          // argmax, first-wins on tie
    float v  = w ? m1 : m0;
    float mn = mm[w], mx = mm[2 + w];
    float lo = w ? 20.0f : 0.0f;
    pos[n] = (v - mn) / (mx - mn + 1e-8f) * 4.0f + lo;
}

// ---------------- tiled SGEMM, C[M,N] = A[M,K] * B[N,K]^T + bias[N] ----------------
// BM=BN=128, BK=8, 256 threads, 8x8 per-thread microtile. N,K multiples of 128/8; M guarded.
__global__ void __launch_bounds__(256) sgemm_nt(const float* __restrict__ A,
                                                const float* __restrict__ B,
                                                const float* __restrict__ bias,
                                                float* __restrict__ C,
                                                int M, int N, int K) {
    __shared__ float As[8][128];
    __shared__ float Bs[8][128];

    int tid = threadIdx.x;
    int tx = tid & 15;          // 0..15  -> N
    int ty = tid >> 4;          // 0..15  -> M
    int row0 = blockIdx.y * 128;
    int col0 = blockIdx.x * 128;

    int lr = tid >> 1;          // 0..127
    int lk = (tid & 1) * 4;     // 0 or 4
    const float* Aptr = A + (size_t)(row0 + lr) * K + lk;
    const float* Bptr = B + (size_t)(col0 + lr) * K + lk;
    bool aval = (row0 + lr) < M;

    float acc[8][8];
    #pragma unroll
    for (int i = 0; i < 8; i++)
        #pragma unroll
        for (int j = 0; j < 8; j++) acc[i][j] = 0.0f;

    for (int k0 = 0; k0 < K; k0 += 8) {
        float4 av = aval ? *(const float4*)(Aptr + k0) : make_float4(0.f, 0.f, 0.f, 0.f);
        float4 bv = *(const float4*)(Bptr + k0);
        As[lk + 0][lr] = av.x; As[lk + 1][lr] = av.y; As[lk + 2][lr] = av.z; As[lk + 3][lr] = av.w;
        Bs[lk + 0][lr] = bv.x; Bs[lk + 1][lr] = bv.y; Bs[lk + 2][lr] = bv.z; Bs[lk + 3][lr] = bv.w;
        __syncthreads();

        #pragma unroll
        for (int kk = 0; kk < 8; kk++) {
            float4 a0 = *(const float4*)(&As[kk][ty * 8]);
            float4 a1 = *(const float4*)(&As[kk][ty * 8 + 4]);
            float4 b0 = *(const float4*)(&Bs[kk][tx * 8]);
            float4 b1 = *(const float4*)(&Bs[kk][tx * 8 + 4]);
            float a[8] = {a0.x, a0.y, a0.z, a0.w, a1.x, a1.y, a1.z, a1.w};
            float b[8] = {b0.x, b0.y, b0.z, b0.w, b1.x, b1.y, b1.z, b1.w};
            #pragma unroll
            for (int i = 0; i < 8; i++)
                #pragma unroll
                for (int j = 0; j < 8; j++) acc[i][j] += a[i] * b[j];
        }
        __syncthreads();
    }

    #pragma unroll
    for (int i = 0; i < 8; i++) {
        int r = row0 + ty * 8 + i;
        if (r >= M) continue;
        int cbase = col0 + tx * 8;
        float4 o0, o1;
        o0.x = acc[i][0] + bias[cbase + 0];
        o0.y = acc[i][1] + bias[cbase + 1];
        o0.z = acc[i][2] + bias[cbase + 2];
        o0.w = acc[i][3] + bias[cbase + 3];
        o1.x = acc[i][4] + bias[cbase + 4];
        o1.y = acc[i][5] + bias[cbase + 5];
        o1.z = acc[i][6] + bias[cbase + 6];
        o1.w = acc[i][7] + bias[cbase + 7];
        *(float4*)(C + (size_t)r * N + cbase)     = o0;
        *(float4*)(C + (size_t)r * N + cbase + 4) = o1;
    }
}

// ---------------- warp+block reduce helper ----------------
__device__ __forceinline__ float block_sum_256(float v, float* red) {
    for (int o = 16; o > 0; o >>= 1) v += __shfl_xor_sync(0xFFFFFFFFu, v, o);
    int warp = threadIdx.x >> 5;
    if ((threadIdx.x & 31) == 0) red[warp] = v;
    __syncthreads();
    float s = 0.f;
    if (threadIdx.x < 8) s = red[threadIdx.x];
    if (threadIdx.x < 32) {
        for (int o = 4; o > 0; o >>= 1) s += __shfl_xor_sync(0xFFFFFFFFu, s, o);
    }
    if (threadIdx.x == 0) red[0] = s;
    __syncthreads();
    return red[0];
}

// ---------------- Q: rmsnorm + rope (in place on g_q) ----------------
__global__ void __launch_bounds__(256) qnorm_rope_kernel(float* __restrict__ q,
                                                         const float* __restrict__ w,
                                                         const float* __restrict__ pos) {
    __shared__ float row[D_MODEL];
    __shared__ float red[8];
    __shared__ float sfreq[64];
    int s   = blockIdx.x;
    int tid = threadIdx.x;
    if (tid < 64) sfreq[tid] = powf(10000.0f, -((float)tid) / 64.0f);

    float* base = q + (size_t)s * D_MODEL;
    int j0 = tid * 8;
    float4 r0 = *(const float4*)(base + j0);
    float4 r1 = *(const float4*)(base + j0 + 4);
    float ss = r0.x*r0.x + r0.y*r0.y + r0.z*r0.z + r0.w*r0.w
             + r1.x*r1.x + r1.y*r1.y + r1.z*r1.z + r1.w*r1.w;
    float tot = block_sum_256(ss, red);
    float scale = rsqrtf(tot / (float)D_MODEL + EPS);

    float4 w0 = *(const float4*)(w + j0);
    float4 w1 = *(const float4*)(w + j0 + 4);
    row[j0 + 0] = r0.x * scale * w0.x;
    row[j0 + 1] = r0.y * scale * w0.y;
    row[j0 + 2] = r0.z * scale * w0.z;
    row[j0 + 3] = r0.w * scale * w0.w;
    row[j0 + 4] = r1.x * scale * w1.x;
    row[j0 + 5] = r1.y * scale * w1.y;
    row[j0 + 6] = r1.z * scale * w1.z;
    row[j0 + 7] = r1.w * scale * w1.w;
    __syncthreads();

    int bt = s / L_TOK;
    int l  = s % L_TOK;
    int h  = j0 >> 7;   // 8 contiguous elems stay inside one head
    float p = pos[((bt * 16 + h) % 21) * L_TOK + l];

    float out[8];
    #pragma unroll
    for (int e = 0; e < 8; e++) {
        int j = j0 + e;
        int c = j & 127;
        float f = p * sfreq[c & 63];
        float sn, cs;
        __sincosf(f, &sn, &cs);
        float partner = (c < 64) ? -row[j + 64] : row[j - 64];
        out[e] = row[j] * cs + partner * sn;
    }
    *(float4*)(base + j0)     = make_float4(out[0], out[1], out[2], out[3]);
    *(float4*)(base + j0 + 4) = make_float4(out[4], out[5], out[6], out[7]);
}

// ---------------- K: rmsnorm + rope (in place on g_k); pos = (a<32)?2:22 ----------------
__global__ void __launch_bounds__(256) knorm_rope_kernel(float* __restrict__ k,
                                                         const float* __restrict__ w) {
    __shared__ float row[D_MODEL];
    __shared__ float red[8];
    __shared__ float sfreq[64];
    int r   = blockIdx.x;   // 0..1343
    int tid = threadIdx.x;
    if (tid < 64) sfreq[tid] = powf(10000.0f, -((float)tid) / 64.0f);

    float* base = k + (size_t)r * D_MODEL;
    int j0 = tid * 8;
    float4 r0 = *(const float4*)(base + j0);
    float4 r1 = *(const float4*)(base + j0 + 4);
    float ss = r0.x*r0.x + r0.y*r0.y + r0.z*r0.z + r0.w*r0.w
             + r1.x*r1.x + r1.y*r1.y + r1.z*r1.z + r1.w*r1.w;
    float tot = block_sum_256(ss, red);
    float scale = rsqrtf(tot / (float)D_MODEL + EPS);

    float4 w0 = *(const float4*)(w + j0);
    float4 w1 = *(const float4*)(w + j0 + 4);
    row[j0 + 0] = r0.x * scale * w0.x;
    row[j0 + 1] = r0.y * scale * w0.y;
    row[j0 + 2] = r0.z * scale * w0.z;
    row[j0 + 3] = r0.w * scale * w0.w;
    row[j0 + 4] = r1.x * scale * w1.x;
    row[j0 + 5] = r1.y * scale * w1.y;
    row[j0 + 6] = r1.z * scale * w1.z;
    row[j0 + 7] = r1.w * scale * w1.w;
    __syncthreads();

    int a = r & 63;
    float p = (a < 32) ? 2.0f : 22.0f;

    float out[8];
    #pragma unroll
    for (int e = 0; e < 8; e++) {
        int j = j0 + e;
        int c = j & 127;
        float f = p * sfreq[c & 63];
        float sn, cs;
        __sincosf(f, &sn, &cs);
        float partner = (c < 64) ? -row[j + 64] : row[j - 64];
        out[e] = row[j] * cs + partner * sn;
    }
    *(float4*)(base + j0)     = make_float4(out[0], out[1], out[2], out[3]);
    *(float4*)(base + j0 + 4) = make_float4(out[4], out[5], out[6], out[7]);
}

// ---------------- cross attention ----------------
// grid.x = BT*H (336), grid.y = ceil(1560/TQ). Dynamic smem = K(32K)+V(32K)+Q(16K)+P(8K) = 88KB.
#define TQ 32
__global__ void __launch_bounds__(256) attn_kernel(const float* __restrict__ q,
                                                   const float* __restrict__ k,
                                                   const float* __restrict__ v,
                                                   float* __restrict__ out) {
    extern __shared__ float sm[];
    float* Ks = sm;                     // 64*128
    float* Vs = Ks + 64 * 128;          // 64*128
    float* Qs = Vs + 64 * 128;          // TQ*128
    float* Ps = Qs + TQ * 128;          // TQ*64

    int bh = blockIdx.x;
    int bt = bh >> 4;
    int h  = bh & 15;
    int l0 = blockIdx.y * TQ;
    int tid = threadIdx.x;
    int nrows = L_TOK - l0; if (nrows > TQ) nrows = TQ;

    // load K,V tiles (64 rows x 128 cols)
    for (int i = tid; i < 64 * 32; i += 256) {
        int a  = i >> 5;
        int c4 = (i & 31) * 4;
        size_t goff = (size_t)(bt * 64 + a) * D_MODEL + h * 128 + c4;
        *(float4*)(Ks + a * 128 + c4) = *(const float4*)(k + goff);
        *(float4*)(Vs + a * 128 + c4) = *(const float4*)(v + goff);
    }
    // load Q tile
    for (int i = tid; i < TQ * 32; i += 256) {
        int r  = i >> 5;
        int c4 = (i & 31) * 4;
        if (r < nrows) {
            size_t goff = (size_t)(bt * L_TOK + l0 + r) * D_MODEL + h * 128 + c4;
            *(float4*)(Qs + r * 128 + c4) = *(const float4*)(q + goff);
        }
    }
    __syncthreads();

    // scores
    for (int i = tid; i < TQ * 64; i += 256) {
        int r = i >> 6;
        int a = i & 63;
        if (r < nrows) {
            float acc = 0.f;
            #pragma unroll 8
            for (int c = 0; c < 128; c++) acc += Qs[r * 128 + c] * Ks[a * 128 + c];
            Ps[r * 64 + a] = acc * ATT_SCALE;
        }
    }
    __syncthreads();

    // softmax over A=64 (one warp per row, 2 elems/lane)
    int warp = tid >> 5, lane = tid & 31;
    for (int r = warp; r < nrows; r += 8) {
        float v0 = Ps[r * 64 + lane];
        float v1 = Ps[r * 64 + 32 + lane];
        float m = fmaxf(v0, v1);
        for (int o = 16; o > 0; o >>= 1) m = fmaxf(m, __shfl_xor_sync(0xFFFFFFFFu, m, o));
        float e0 = expf(v0 - m), e1 = expf(v1 - m);
        float su = e0 + e1;
        for (int o = 16; o > 0; o >>= 1) su += __shfl_xor_sync(0xFFFFFFFFu, su, o);
        float inv = 1.0f / su;
        Ps[r * 64 + lane]      = e0 * inv;
        Ps[r * 64 + 32 + lane] = e1 * inv;
    }
    __syncthreads();

    // out = P @ V
    for (int i = tid; i < TQ * 128; i += 256) {
        int r = i >> 7;
        int c = i & 127;
        if (r < nrows) {
            float acc = 0.f;
            #pragma unroll 8
            for (int a = 0; a < 64; a++) acc += Ps[r * 64 + a] * Vs[a * 128 + c];
            out[(size_t)(bt * L_TOK + l0 + r) * D_MODEL + h * 128 + c] = acc;
        }
    }
}

// ---------------- launcher ----------------
extern "C" void kernel_launch(void* const* d_in, const int* in_sizes, int n_in,
                              void* d_out, int out_size) {
    const float* hidden = (const float*)d_in[0];
    const float* enc    = (const float*)d_in[1];
    const float* maps   = (const float*)d_in[2];
    const float* qw     = (const float*)d_in[3];
    const float* qb     = (const float*)d_in[4];
    const float* kw     = (const float*)d_in[5];
    const float* kb     = (const float*)d_in[6];
    const float* vw     = (const float*)d_in[7];
    const float* vb     = (const float*)d_in[8];
    const float* ow     = (const float*)d_in[9];
    const float* ob     = (const float*)d_in[10];
    const float* nqw    = (const float*)d_in[11];
    const float* nkw    = (const float*)d_in[12];
    float* outp = (float*)d_out;

    void *pq, *patt, *pk, *pv, *ppos, *pmm;
    cudaGetSymbolAddress(&pq,   g_q);
    cudaGetSymbolAddress(&patt, g_att);
    cudaGetSymbolAddress(&pk,   g_k);
    cudaGetSymbolAddress(&pv,   g_v);
    cudaGetSymbolAddress(&ppos, g_pos);
    cudaGetSymbolAddress(&pmm,  g_mm);

    // 1) per-stream min/max, 2) position ids
    minmax_kernel<<<2, 256>>>(maps, (float*)pmm);
    pos_kernel<<<(S_TOK + 255) / 256, 256>>>(maps, (const float*)pmm, (float*)ppos);

    // 3-5) projections
    {
        dim3 gkv(D_MODEL / 128, (KV_ROWS + 127) / 128);      // 16 x 11
        sgemm_nt<<<gkv, 256>>>(enc, kw, kb, (float*)pk, KV_ROWS, D_MODEL, D_MODEL);
        sgemm_nt<<<gkv, 256>>>(enc, vw, vb, (float*)pv, KV_ROWS, D_MODEL, D_MODEL);
        dim3 gq(D_MODEL / 128, (S_TOK + 127) / 128);         // 16 x 256
        sgemm_nt<<<gq, 256>>>(hidden, qw, qb, (float*)pq, S_TOK, D_MODEL, D_MODEL);
    }

    // 6-7) rmsnorm + rope
    knorm_rope_kernel<<<KV_ROWS, 256>>>((float*)pk, nkw);
    qnorm_rope_kernel<<<S_TOK, 256>>>((float*)pq, nqw, (const float*)ppos);

    // 8) attention
    {
        int smem = (64 * 128 * 2 + TQ * 128 + TQ * 64) * sizeof(float);  // 90112 B
        cudaFuncSetAttribute(attn_kernel, cudaFuncAttributeMaxDynamicSharedMemorySize, smem);
        dim3 ga(T_GRID * N_HEADS, (L_TOK + TQ - 1) / TQ);    // 336 x 49
        attn_kernel<<<ga, 256, smem>>>((const float*)pq, (const float*)pk, (const float*)pv, (float*)patt);
    }

    // 9) output projection -> d_out
    {
        dim3 go(D_MODEL / 128, (S_TOK + 127) / 128);
        sgemm_nt<<<go, 256>>>((const float*)patt, ow, ob, outp, S_TOK, D_MODEL, D_MODEL);
    }
}